// round 4
// baseline (speedup 1.0000x reference)
#include <cuda_runtime.h>

// Problem constants (fixed shapes from reference setup_inputs):
//   x, out_ae : (16, 3, 512, 512) fp32
//   out_seg   : (16, 1, 512, 512) fp32
//   out       : scalar fp32 loss
#define N_      16
#define C_      3
#define HW_     (512 * 512)          // 262144
#define NHW_    (N_ * HW_)           // 4194304  (seg element count, = pos+neg total)
#define HW4_    (HW_ / 4)            // 65536    (float4 units per plane)
#define NHW4_   (NHW_ / 4)           // 1048576  (float4 work items)
#define BF_THRESH 0.5f

#define BLOCK_THREADS 256
#define GRID_BLOCKS   2048           // 2 float4-items per thread

// Device-global accumulators. Zero-initialized at module load; the
// finalizing block resets them to zero so every graph replay starts clean.
__device__ float        g_pos_sum = 0.0f;
__device__ float        g_tot_sum = 0.0f;
__device__ float        g_pos_cnt = 0.0f;
__device__ unsigned int g_done    = 0u;

__global__ __launch_bounds__(BLOCK_THREADS)
void wmse_kernel(const float4* __restrict__ x4,
                 const float4* __restrict__ ae4,
                 const float4* __restrict__ seg4,
                 float* __restrict__ out)
{
    float pos_s = 0.0f;   // sum of diff^2 where seg > 0.5 (over all c)
    float tot_s = 0.0f;   // sum of diff^2 over everything
    float cnt   = 0.0f;   // count of seg > 0.5 (over n,h,w only)

    const int stride = gridDim.x * blockDim.x;
    for (int g = blockIdx.x * blockDim.x + threadIdx.x; g < NHW4_; g += stride) {
        // g indexes float4 groups over (n, h*w/4). HW4_ = 65536 = 2^16.
        const int n   = g >> 16;
        const int hwq = g & 0xFFFF;

        const float4 s = seg4[g];
        const float4 p = make_float4(s.x > BF_THRESH ? 1.0f : 0.0f,
                                     s.y > BF_THRESH ? 1.0f : 0.0f,
                                     s.z > BF_THRESH ? 1.0f : 0.0f,
                                     s.w > BF_THRESH ? 1.0f : 0.0f);
        cnt += (p.x + p.y) + (p.z + p.w);

        const int base = n * (C_ * HW4_) + hwq;
        #pragma unroll
        for (int c = 0; c < C_; ++c) {
            const float4 xv = x4 [base + c * HW4_];
            const float4 av = ae4[base + c * HW4_];
            const float dx = av.x - xv.x;
            const float dy = av.y - xv.y;
            const float dz = av.z - xv.z;
            const float dw = av.w - xv.w;
            const float ex = dx * dx, ey = dy * dy, ez = dz * dz, ew = dw * dw;
            tot_s += (ex + ey) + (ez + ew);
            pos_s += (ex * p.x + ey * p.y) + (ez * p.z + ew * p.w);
        }
    }

    // ---- intra-warp reduction ----
    #pragma unroll
    for (int o = 16; o > 0; o >>= 1) {
        pos_s += __shfl_down_sync(0xFFFFFFFFu, pos_s, o);
        tot_s += __shfl_down_sync(0xFFFFFFFFu, tot_s, o);
        cnt   += __shfl_down_sync(0xFFFFFFFFu, cnt,   o);
    }

    // ---- intra-block reduction (8 warps) ----
    __shared__ float sp[8], st[8], sc[8];
    const int wid = threadIdx.x >> 5;
    const int lid = threadIdx.x & 31;
    if (lid == 0) { sp[wid] = pos_s; st[wid] = tot_s; sc[wid] = cnt; }
    __syncthreads();

    if (threadIdx.x == 0) {
        float bp = 0.0f, bt = 0.0f, bc = 0.0f;
        #pragma unroll
        for (int i = 0; i < BLOCK_THREADS / 32; ++i) {
            bp += sp[i]; bt += st[i]; bc += sc[i];
        }

        atomicAdd(&g_pos_sum, bp);
        atomicAdd(&g_tot_sum, bt);
        atomicAdd(&g_pos_cnt, bc);
        __threadfence();

        const unsigned int ticket = atomicAdd(&g_done, 1u);
        if (ticket == gridDim.x - 1u) {
            // Last block: all partials are globally visible. Read via
            // atomic (returns old value) to avoid any stale-cache concern.
            const float ps = atomicAdd(&g_pos_sum, 0.0f);
            const float ts = atomicAdd(&g_tot_sum, 0.0f);
            const float pn = atomicAdd(&g_pos_cnt, 0.0f);

            const float total     = (float)NHW_;
            const float neg_num   = total - pn;
            const float pos_ratio = pn / total;
            const float neg_ratio = 1.0f - pos_ratio;
            const float cf        = (float)C_;
            const float mse_pos   = ps / (pn * cf);
            const float mse_neg   = (ts - ps) / (neg_num * cf);
            out[0] = pos_ratio * mse_neg + neg_ratio * mse_pos;

            // Reset accumulators so the next graph replay starts clean.
            g_pos_sum = 0.0f;
            g_tot_sum = 0.0f;
            g_pos_cnt = 0.0f;
            __threadfence();
            g_done = 0u;
        }
    }
}

extern "C" void kernel_launch(void* const* d_in, const int* in_sizes, int n_in,
                              void* d_out, int out_size)
{
    const float4* x4   = (const float4*)d_in[0];   // x        (16,3,512,512)
    const float4* ae4  = (const float4*)d_in[1];   // out_ae   (16,3,512,512)
    const float4* seg4 = (const float4*)d_in[2];   // out_seg  (16,1,512,512)
    float* out = (float*)d_out;

    wmse_kernel<<<GRID_BLOCKS, BLOCK_THREADS>>>(x4, ae4, seg4, out);
}